// round 6
// baseline (speedup 1.0000x reference)
#include <cuda_runtime.h>

// InputDefenseLayer: y[b,0,c] = clip(x[b,0,c]); y[b,t,c] = 0.25*clip(x[b,t,c]) + 0.75*y[b,t-1,c]
//
// Chunked-scan with halo warmup: 0.75^128 ~ 1e-16, so a 128-step warmup makes each
// chunk's recurrence exact to fp32 regardless of init. 8 chunks x 64 batches = 512
// independent units; each unit = 64 threads, one float4 (4 channels) per thread.

static constexpr int B_DIM  = 64;
static constexpr int T_DIM  = 2048;
static constexpr int C_DIM  = 256;
static constexpr int C4     = C_DIM / 4;     // 64 float4 lanes per (b,t) row

static constexpr int CHUNK  = 256;           // stored timesteps per unit
static constexpr int HALO   = 128;           // warmup steps (0.75^128 ~ 1.1e-16)
static constexpr int NCHUNK = T_DIM / CHUNK; // 8

static constexpr float A_COEF = 0.25f;
static constexpr float B_COEF = 0.75f;
static constexpr float CLIP_MIN = -3.5f;
static constexpr float CLIP_MAX =  3.5f;

__device__ __forceinline__ float4 clip4(float4 v) {
    v.x = fminf(fmaxf(v.x, CLIP_MIN), CLIP_MAX);
    v.y = fminf(fmaxf(v.y, CLIP_MIN), CLIP_MAX);
    v.z = fminf(fmaxf(v.z, CLIP_MIN), CLIP_MAX);
    v.w = fminf(fmaxf(v.w, CLIP_MIN), CLIP_MAX);
    return v;
}

__device__ __forceinline__ float4 ema4(float4 s, float4 x) {
    s.x = fmaf(A_COEF, x.x, B_COEF * s.x);
    s.y = fmaf(A_COEF, x.y, B_COEF * s.y);
    s.z = fmaf(A_COEF, x.z, B_COEF * s.z);
    s.w = fmaf(A_COEF, x.w, B_COEF * s.w);
    return s;
}

__global__ __launch_bounds__(64)
void ema_scan_kernel(const float4* __restrict__ x, float4* __restrict__ y) {
    const int unit  = blockIdx.x;           // 0 .. B_DIM*NCHUNK-1
    const int b     = unit / NCHUNK;
    const int chunk = unit - b * NCHUNK;
    const int lane  = threadIdx.x;          // 0 .. 63 (float4 lane within channel row)

    const float4* __restrict__ xi = x + (size_t)b * T_DIM * C4 + lane;
    float4*       __restrict__ yo = y + (size_t)b * T_DIM * C4 + lane;

    const int t0 = chunk * CHUNK;                    // first stored timestep
    const int ts = (chunk == 0) ? 0 : (t0 - HALO);   // first loaded timestep

    // Init: exact for chunk 0 (s_0 = clip(x_0)); for others any bounded init works,
    // error decays by 0.75^HALO before the first store.
    float4 s = clip4(xi[(size_t)ts * C4]);
    if (chunk == 0) {
        yo[0] = s;
    }

    // Halo warmup (empty for chunk 0). Loads are independent of s, so the
    // unrolled body batches 8 outstanding LDG.128 per thread.
    #pragma unroll 8
    for (int t = ts + 1; t < t0; ++t) {
        s = ema4(s, clip4(xi[(size_t)t * C4]));
    }

    // Main stored region.
    const int tb = (chunk == 0) ? 1 : t0;
    #pragma unroll 8
    for (int t = tb; t < t0 + CHUNK; ++t) {
        s = ema4(s, clip4(xi[(size_t)t * C4]));
        yo[(size_t)t * C4] = s;
    }
}

extern "C" void kernel_launch(void* const* d_in, const int* in_sizes, int n_in,
                              void* d_out, int out_size) {
    const float4* x = (const float4*)d_in[0];
    float4*       y = (float4*)d_out;
    ema_scan_kernel<<<B_DIM * NCHUNK, 64>>>(x, y);
}

// round 7
// speedup vs baseline: 1.0123x; 1.0123x over previous
#include <cuda_runtime.h>

// InputDefenseLayer: y[b,0,c] = clip(x[b,0,c]); y[b,t,c] = 0.25*clip(x[b,t,c]) + 0.75*y[b,t-1,c]
//
// Chunked-scan with halo warmup: 0.75^128 ~ 1e-16, so a 128-step warmup makes each
// chunk's recurrence exact to fp32 regardless of init. 8 chunks x 64 batches = 512
// independent units; each unit = 64 threads, one float4 (4 channels) per thread.

static constexpr int B_DIM  = 64;
static constexpr int T_DIM  = 2048;
static constexpr int C_DIM  = 256;
static constexpr int C4     = C_DIM / 4;     // 64 float4 lanes per (b,t) row

static constexpr int CHUNK  = 256;           // stored timesteps per unit
static constexpr int HALO   = 128;           // warmup steps (0.75^128 ~ 1.1e-16)
static constexpr int NCHUNK = T_DIM / CHUNK; // 8

static constexpr float A_COEF = 0.25f;
static constexpr float B_COEF = 0.75f;
static constexpr float CLIP_MIN = -3.5f;
static constexpr float CLIP_MAX =  3.5f;

__device__ __forceinline__ float4 clip4(float4 v) {
    v.x = fminf(fmaxf(v.x, CLIP_MIN), CLIP_MAX);
    v.y = fminf(fmaxf(v.y, CLIP_MIN), CLIP_MAX);
    v.z = fminf(fmaxf(v.z, CLIP_MIN), CLIP_MAX);
    v.w = fminf(fmaxf(v.w, CLIP_MIN), CLIP_MAX);
    return v;
}

__device__ __forceinline__ float4 ema4(float4 s, float4 x) {
    s.x = fmaf(A_COEF, x.x, B_COEF * s.x);
    s.y = fmaf(A_COEF, x.y, B_COEF * s.y);
    s.z = fmaf(A_COEF, x.z, B_COEF * s.z);
    s.w = fmaf(A_COEF, x.w, B_COEF * s.w);
    return s;
}

__global__ __launch_bounds__(64)
void ema_scan_kernel(const float4* __restrict__ x, float4* __restrict__ y) {
    const int unit  = blockIdx.x;           // 0 .. B_DIM*NCHUNK-1
    const int b     = unit / NCHUNK;
    const int chunk = unit - b * NCHUNK;
    const int lane  = threadIdx.x;          // 0 .. 63 (float4 lane within channel row)

    const float4* __restrict__ xi = x + (size_t)b * T_DIM * C4 + lane;
    float4*       __restrict__ yo = y + (size_t)b * T_DIM * C4 + lane;

    const int t0 = chunk * CHUNK;                    // first stored timestep
    const int ts = (chunk == 0) ? 0 : (t0 - HALO);   // first loaded timestep

    // Init: exact for chunk 0 (s_0 = clip(x_0)); for others any bounded init works,
    // error decays by 0.75^HALO before the first store.
    float4 s = clip4(xi[(size_t)ts * C4]);
    if (chunk == 0) {
        yo[0] = s;
    }

    // Halo warmup (empty for chunk 0). Loads are independent of s, so the
    // unrolled body batches 8 outstanding LDG.128 per thread.
    #pragma unroll 8
    for (int t = ts + 1; t < t0; ++t) {
        s = ema4(s, clip4(xi[(size_t)t * C4]));
    }

    // Main stored region.
    const int tb = (chunk == 0) ? 1 : t0;
    #pragma unroll 8
    for (int t = tb; t < t0 + CHUNK; ++t) {
        s = ema4(s, clip4(xi[(size_t)t * C4]));
        yo[(size_t)t * C4] = s;
    }
}

extern "C" void kernel_launch(void* const* d_in, const int* in_sizes, int n_in,
                              void* d_out, int out_size) {
    const float4* x = (const float4*)d_in[0];
    float4*       y = (float4*)d_out;
    ema_scan_kernel<<<B_DIM * NCHUNK, 64>>>(x, y);
}

// round 8
// speedup vs baseline: 1.0130x; 1.0008x over previous
#include <cuda_runtime.h>

// InputDefenseLayer: y[b,0,c] = clip(x[b,0,c]); y[b,t,c] = 0.25*clip(x[b,t,c]) + 0.75*y[b,t-1,c]
//
// Chunked-scan with halo warmup: 0.75^128 ~ 1e-16, so a 128-step warmup makes each
// chunk's recurrence exact to fp32 regardless of init. 8 chunks x 64 batches = 512
// independent units; each unit = 64 threads, one float4 (4 channels) per thread.

static constexpr int B_DIM  = 64;
static constexpr int T_DIM  = 2048;
static constexpr int C_DIM  = 256;
static constexpr int C4     = C_DIM / 4;     // 64 float4 lanes per (b,t) row

static constexpr int CHUNK  = 256;           // stored timesteps per unit
static constexpr int HALO   = 128;           // warmup steps (0.75^128 ~ 1.1e-16)
static constexpr int NCHUNK = T_DIM / CHUNK; // 8

static constexpr float A_COEF = 0.25f;
static constexpr float B_COEF = 0.75f;
static constexpr float CLIP_MIN = -3.5f;
static constexpr float CLIP_MAX =  3.5f;

__device__ __forceinline__ float4 clip4(float4 v) {
    v.x = fminf(fmaxf(v.x, CLIP_MIN), CLIP_MAX);
    v.y = fminf(fmaxf(v.y, CLIP_MIN), CLIP_MAX);
    v.z = fminf(fmaxf(v.z, CLIP_MIN), CLIP_MAX);
    v.w = fminf(fmaxf(v.w, CLIP_MIN), CLIP_MAX);
    return v;
}

__device__ __forceinline__ float4 ema4(float4 s, float4 x) {
    s.x = fmaf(A_COEF, x.x, B_COEF * s.x);
    s.y = fmaf(A_COEF, x.y, B_COEF * s.y);
    s.z = fmaf(A_COEF, x.z, B_COEF * s.z);
    s.w = fmaf(A_COEF, x.w, B_COEF * s.w);
    return s;
}

__global__ __launch_bounds__(64)
void ema_scan_kernel(const float4* __restrict__ x, float4* __restrict__ y) {
    const int unit  = blockIdx.x;           // 0 .. B_DIM*NCHUNK-1
    const int b     = unit / NCHUNK;
    const int chunk = unit - b * NCHUNK;
    const int lane  = threadIdx.x;          // 0 .. 63 (float4 lane within channel row)

    const float4* __restrict__ xi = x + (size_t)b * T_DIM * C4 + lane;
    float4*       __restrict__ yo = y + (size_t)b * T_DIM * C4 + lane;

    const int t0 = chunk * CHUNK;                    // first stored timestep
    const int ts = (chunk == 0) ? 0 : (t0 - HALO);   // first loaded timestep

    // Init: exact for chunk 0 (s_0 = clip(x_0)); for others any bounded init works,
    // error decays by 0.75^HALO before the first store.
    float4 s = clip4(xi[(size_t)ts * C4]);
    if (chunk == 0) {
        yo[0] = s;
    }

    // Halo warmup (empty for chunk 0). Loads are independent of s, so the
    // unrolled body batches 8 outstanding LDG.128 per thread.
    #pragma unroll 8
    for (int t = ts + 1; t < t0; ++t) {
        s = ema4(s, clip4(xi[(size_t)t * C4]));
    }

    // Main stored region.
    const int tb = (chunk == 0) ? 1 : t0;
    #pragma unroll 8
    for (int t = tb; t < t0 + CHUNK; ++t) {
        s = ema4(s, clip4(xi[(size_t)t * C4]));
        yo[(size_t)t * C4] = s;
    }
}

extern "C" void kernel_launch(void* const* d_in, const int* in_sizes, int n_in,
                              void* d_out, int out_size) {
    const float4* x = (const float4*)d_in[0];
    float4*       y = (float4*)d_out;
    ema_scan_kernel<<<B_DIM * NCHUNK, 64>>>(x, y);
}

// round 9
// speedup vs baseline: 1.3643x; 1.3468x over previous
#include <cuda_runtime.h>

// InputDefenseLayer: y[b,0,c] = clip(x[b,0,c]); y[b,t,c] = 0.25*clip(x[b,t,c]) + 0.75*y[b,t-1,c]
//
// Chunked-scan with halo warmup. 0.75^47 ~ 1.3e-6, so a 48-step warmup bounds the
// init error at ~9e-6 absolute (~2e-5 relative to output norm), far below the 1e-3
// threshold. 16 chunks x 64 batches = 1024 independent units (=> ~14 warps/SM,
// double R7's occupancy to hide DRAM latency); each unit = 64 threads, one float4
// (4 channels) per thread, fully coalesced 1KB-row accesses.

static constexpr int B_DIM  = 64;
static constexpr int T_DIM  = 2048;
static constexpr int C_DIM  = 256;
static constexpr int C4     = C_DIM / 4;     // 64 float4 lanes per (b,t) row

static constexpr int CHUNK  = 128;           // stored timesteps per unit
static constexpr int HALO   = 48;            // warmup steps (err ~ 7*0.75^47 ~ 9e-6)
static constexpr int NCHUNK = T_DIM / CHUNK; // 16

static constexpr float A_COEF = 0.25f;
static constexpr float B_COEF = 0.75f;
static constexpr float CLIP_MIN = -3.5f;
static constexpr float CLIP_MAX =  3.5f;

__device__ __forceinline__ float4 clip4(float4 v) {
    v.x = fminf(fmaxf(v.x, CLIP_MIN), CLIP_MAX);
    v.y = fminf(fmaxf(v.y, CLIP_MIN), CLIP_MAX);
    v.z = fminf(fmaxf(v.z, CLIP_MIN), CLIP_MAX);
    v.w = fminf(fmaxf(v.w, CLIP_MIN), CLIP_MAX);
    return v;
}

__device__ __forceinline__ float4 ema4(float4 s, float4 x) {
    s.x = fmaf(A_COEF, x.x, B_COEF * s.x);
    s.y = fmaf(A_COEF, x.y, B_COEF * s.y);
    s.z = fmaf(A_COEF, x.z, B_COEF * s.z);
    s.w = fmaf(A_COEF, x.w, B_COEF * s.w);
    return s;
}

__global__ __launch_bounds__(64)
void ema_scan_kernel(const float4* __restrict__ x, float4* __restrict__ y) {
    const int unit  = blockIdx.x;           // 0 .. B_DIM*NCHUNK-1
    const int b     = unit >> 4;            // unit / NCHUNK
    const int chunk = unit & (NCHUNK - 1);
    const int lane  = threadIdx.x;          // 0 .. 63 (float4 lane within channel row)

    const float4* __restrict__ xi = x + (size_t)b * T_DIM * C4 + lane;
    float4*       __restrict__ yo = y + (size_t)b * T_DIM * C4 + lane;

    const int t0 = chunk * CHUNK;                    // first stored timestep
    const int ts = (chunk == 0) ? 0 : (t0 - HALO);   // first loaded timestep

    // Init: exact for chunk 0 (s_0 = clip(x_0)); for others any bounded init works,
    // error decays by 0.75^(HALO-1) before the first store.
    float4 s = clip4(xi[(size_t)ts * C4]);
    if (chunk == 0) {
        yo[0] = s;
    }

    // Halo warmup (empty for chunk 0). Loads are independent of s, so the
    // unrolled body batches 8 outstanding LDG.128 per thread.
    #pragma unroll 8
    for (int t = ts + 1; t < t0; ++t) {
        s = ema4(s, clip4(xi[(size_t)t * C4]));
    }

    // Main stored region. Streaming stores (.cs): output is never re-read,
    // keep it from evicting halo lines other CTAs will re-read from L2.
    const int tb = (chunk == 0) ? 1 : t0;
    #pragma unroll 8
    for (int t = tb; t < t0 + CHUNK; ++t) {
        s = ema4(s, clip4(xi[(size_t)t * C4]));
        __stcs(&yo[(size_t)t * C4], s);
    }
}

extern "C" void kernel_launch(void* const* d_in, const int* in_sizes, int n_in,
                              void* d_out, int out_size) {
    const float4* x = (const float4*)d_in[0];
    float4*       y = (float4*)d_out;
    ema_scan_kernel<<<B_DIM * NCHUNK, 64>>>(x, y);
}

// round 10
// speedup vs baseline: 1.6398x; 1.2019x over previous
#include <cuda_runtime.h>

// InputDefenseLayer: y[b,0,c] = clip(x[b,0,c]); y[b,t,c] = 0.25*clip(x[b,t,c]) + 0.75*y[b,t-1,c]
//
// Chunked scan with halo warmup (0.75^48 ~ 1e-6 -> init error far below 1e-3 threshold).
// 16 chunks x 64 batches = 1024 CTAs of 64 threads (one float4 lane each).
// Explicit 8-deep double-buffered prefetch keeps ~8 LDG.128 in flight per thread
// (R9's implicit unroll was capped at ~4 by ptxas's 40-reg heuristic).
// EMA chain written as s = fma(0.75, s, 0.25*x): the multiply is off the serial chain.

static constexpr int B_DIM  = 64;
static constexpr int T_DIM  = 2048;
static constexpr int C4     = 64;            // 256 channels / 4 = float4 lanes per row

static constexpr int CHUNK  = 128;           // stored timesteps per unit
static constexpr int HALO   = 48;            // warmup steps (err ~ 7*0.75^48 ~ 7e-6)
static constexpr int NCHUNK = T_DIM / CHUNK; // 16
static constexpr int U      = 8;             // pipeline group size

static constexpr float A_COEF = 0.25f;
static constexpr float B_COEF = 0.75f;
static constexpr float CLIP_MIN = -3.5f;
static constexpr float CLIP_MAX =  3.5f;

__device__ __forceinline__ float4 clip4(float4 v) {
    v.x = fminf(fmaxf(v.x, CLIP_MIN), CLIP_MAX);
    v.y = fminf(fmaxf(v.y, CLIP_MIN), CLIP_MAX);
    v.z = fminf(fmaxf(v.z, CLIP_MIN), CLIP_MAX);
    v.w = fminf(fmaxf(v.w, CLIP_MIN), CLIP_MAX);
    return v;
}

// Serial chain is a single FMA per step: ax = A*x is independent of s.
__device__ __forceinline__ float4 ema4(float4 s, float4 x) {
    s.x = fmaf(B_COEF, s.x, A_COEF * x.x);
    s.y = fmaf(B_COEF, s.y, A_COEF * x.y);
    s.z = fmaf(B_COEF, s.z, A_COEF * x.z);
    s.w = fmaf(B_COEF, s.w, A_COEF * x.w);
    return s;
}

__global__ __launch_bounds__(64)
void ema_scan_kernel(const float4* __restrict__ x, float4* __restrict__ y) {
    const int unit  = blockIdx.x;           // 0 .. B_DIM*NCHUNK-1
    const int b     = unit >> 4;            // unit / NCHUNK
    const int chunk = unit & (NCHUNK - 1);
    const int lane  = threadIdx.x;          // 0 .. 63

    const float4* __restrict__ xi = x + (size_t)b * T_DIM * C4 + lane;
    float4*       __restrict__ yo = y + (size_t)b * T_DIM * C4 + lane;

    const int t0     = chunk * CHUNK;                  // first stored timestep
    const int tstart = (chunk == 0) ? 0 : (t0 - HALO); // first loaded timestep
    const int tEnd   = t0 + CHUNK;

    // Init. Exact for chunk 0; for others error decays by 0.75^HALO before first store.
    float4 s = clip4(xi[(size_t)tstart * C4]);
    if (chunk == 0) __stcs(&yo[0], s);

    // 7-step prologue: makes remaining step count (127 or 175 -> 120 or 168) a multiple of U.
    #pragma unroll
    for (int j = 1; j <= 7; ++j) {
        s = ema4(s, clip4(xi[(size_t)(tstart + j) * C4]));
        if (chunk == 0) __stcs(&yo[(size_t)j * C4], s);
    }

    int tc = tstart + 8;                      // next compute timestep
    const int nGroups = (tEnd - tc) >> 3;     // 15 (chunk 0) or 21

    float4 bufA[U], bufB[U];
    #pragma unroll
    for (int j = 0; j < U; ++j) bufA[j] = xi[(size_t)(tc + j) * C4];

    for (int g = 0; g < nGroups; ++g) {
        const bool more = (g + 1 < nGroups);
        if (more) {
            #pragma unroll
            for (int j = 0; j < U; ++j) bufB[j] = xi[(size_t)(tc + U + j) * C4];
        }
        #pragma unroll
        for (int j = 0; j < U; ++j) {
            s = ema4(s, clip4(bufA[j]));
            if (tc + j >= t0) __stcs(&yo[(size_t)(tc + j) * C4], s);
        }
        if (more) {
            #pragma unroll
            for (int j = 0; j < U; ++j) bufA[j] = bufB[j];
        }
        tc += U;
    }
}

extern "C" void kernel_launch(void* const* d_in, const int* in_sizes, int n_in,
                              void* d_out, int out_size) {
    const float4* x = (const float4*)d_in[0];
    float4*       y = (float4*)d_out;
    ema_scan_kernel<<<B_DIM * NCHUNK, 64>>>(x, y);
}